// round 3
// baseline (speedup 1.0000x reference)
#include <cuda_runtime.h>
#include <math.h>

// Problem constants
#define BB 2
#define NN 10000
#define HH 128
#define EE 128000
#define MM (BB*EE)          // 256000 rows
#define GDIM 384            // 3*H

typedef unsigned long long ull;

// ---------------- scratch (device globals; no runtime allocation) -------------
__device__ float g_x0[(size_t)MM*128];       // gathered h_target
__device__ float g_x1[(size_t)MM*128];       // gathered h_source
__device__ float g_gi[(size_t)MM*384];       // x @ W_ih^T
__device__ float g_gh[(size_t)MM*384];       // h @ W_hh^T
__device__ float g_y0[(size_t)MM*256];       // layer0 out t=0 [f0|b0]
__device__ float g_y1[(size_t)MM*256];       // layer0 out t=1 [f1|b1]
__device__ float g_hh[(size_t)MM*256];       // layer1 out t=0 [f0'|b0']
__device__ float g_hb1[(size_t)MM*128];      // layer1 backward t=1 state
__device__ float g_logits[MM];               // (B,E) gelu logits
__device__ float g_av[MM];                   // (E,B) (l+g)/tau
__device__ float g_gum[MM];                  // (E,B) gumbel noise
__device__ unsigned g_mxh[NN*BB];
__device__ unsigned g_mxs[NN*BB];
__device__ float g_sh[NN*BB];
__device__ float g_ss[NN*BB];

// ---------------- helpers -----------------------------------------------------
__device__ __forceinline__ unsigned enc_f(float x) {
    unsigned u = __float_as_uint(x);
    return (u & 0x80000000u) ? ~u : (u | 0x80000000u);
}
__device__ __forceinline__ float dec_f(unsigned v) {
    return (v & 0x80000000u) ? __uint_as_float(v ^ 0x80000000u) : __uint_as_float(~v);
}
#define ENC_NEG_INF 0x007FFFFFu   // enc(-inf)

__device__ __forceinline__ float sigmoidf_(float x) { return 1.0f / (1.0f + expf(-x)); }

// packed f32x2 helpers (FFMA2 is only reachable via PTX fma.rn.f32x2)
__device__ __forceinline__ ull pack2_dup(float x) {
    ull r; asm("mov.b64 %0, {%1, %1};" : "=l"(r) : "f"(x)); return r;
}
__device__ __forceinline__ ull fma2(ull a, ull b, ull c) {
    ull d; asm("fma.rn.f32x2 %0, %1, %2, %3;" : "=l"(d) : "l"(a), "l"(b), "l"(c)); return d;
}

// ---------------- gather ------------------------------------------------------
__global__ void gather_kernel(const float4* __restrict__ h,
                              const int* __restrict__ tgt,
                              const int* __restrict__ src,
                              float4* __restrict__ x0, float4* __restrict__ x1) {
    long long idx = (long long)blockIdx.x * blockDim.x + threadIdx.x; // B*E*32
    int q = (int)(idx & 31);
    long long be = idx >> 5;                 // m = b*E + e
    int e = (int)(be % EE);
    int b = (int)(be / EE);
    int t = tgt[e], s = src[e];
    x0[be * 32 + q] = h[((long long)b * NN + t) * 32 + q];
    x1[be * 32 + q] = h[((long long)b * NN + s) * 32 + q];
}

// ---------------- SGEMM (FFMA2): C[M x 384] = A[M x K] * W^T ------------------
#define BM 64
#define BN 64
#define BK 32
#define SPAD 68   // 68 floats = 272 B row stride (divisible by 16 -> float4/ull2 ok)

__global__ void __launch_bounds__(128) sgemm_nt(const float* __restrict__ A, int lda,
                         const float* __restrict__ W, int K,
                         float* __restrict__ C) {
    __shared__ __align__(16) float As[BK][SPAD];
    __shared__ __align__(16) float Bs[BK][SPAD];
    int tid = threadIdx.x;
    int rowBlk = blockIdx.y * BM;
    int colBlk = blockIdx.x * BN;
    int rg = tid & 15;
    int cg = tid >> 4;
    int r0 = rg * 4, c0 = cg * 8;

    ull acc[4][4];   // 4 rows x 4 col-pairs (8 columns)
    #pragma unroll
    for (int i = 0; i < 4; i++)
        #pragma unroll
        for (int j = 0; j < 4; j++) acc[i][j] = 0ull;

    int lrow = tid >> 3;            // 0..15
    int lcol4 = (tid & 7) * 4;      // 0,4,...,28

    for (int kt = 0; kt < K; kt += BK) {
        #pragma unroll
        for (int w = 0; w < 4; w++) {
            int r = lrow + w * 16;
            float4 v = *(const float4*)(A + (size_t)(rowBlk + r) * lda + kt + lcol4);
            As[lcol4 + 0][r] = v.x; As[lcol4 + 1][r] = v.y;
            As[lcol4 + 2][r] = v.z; As[lcol4 + 3][r] = v.w;
        }
        #pragma unroll
        for (int w = 0; w < 4; w++) {
            int r = lrow + w * 16;
            float4 v = *(const float4*)(W + (size_t)(colBlk + r) * K + kt + lcol4);
            Bs[lcol4 + 0][r] = v.x; Bs[lcol4 + 1][r] = v.y;
            Bs[lcol4 + 2][r] = v.z; Bs[lcol4 + 3][r] = v.w;
        }
        __syncthreads();
        #pragma unroll
        for (int k = 0; k < BK; k++) {
            float4 a4 = *(const float4*)&As[k][r0];
            ull Ap[4];
            Ap[0] = pack2_dup(a4.x); Ap[1] = pack2_dup(a4.y);
            Ap[2] = pack2_dup(a4.z); Ap[3] = pack2_dup(a4.w);
            ulonglong2 bA = *(const ulonglong2*)&Bs[k][c0];
            ulonglong2 bB = *(const ulonglong2*)&Bs[k][c0 + 4];
            ull Bv[4] = {bA.x, bA.y, bB.x, bB.y};
            #pragma unroll
            for (int i = 0; i < 4; i++)
                #pragma unroll
                for (int j = 0; j < 4; j++)
                    acc[i][j] = fma2(Ap[i], Bv[j], acc[i][j]);
        }
        __syncthreads();
    }
    #pragma unroll
    for (int i = 0; i < 4; i++) {
        size_t row = (size_t)(rowBlk + r0 + i);
        ulonglong2 v0; v0.x = acc[i][0]; v0.y = acc[i][1];
        ulonglong2 v1; v1.x = acc[i][2]; v1.y = acc[i][3];
        *(ulonglong2*)(C + row * GDIM + colBlk + c0)     = v0;
        *(ulonglong2*)(C + row * GDIM + colBlk + c0 + 4) = v1;
    }
}

// ---------------- GRU pointwise ------------------------------------------------
__global__ void gru_pointwise(const float* __restrict__ gi,
                              const float* __restrict__ gh,      // may be null (h_prev == 0)
                              const float* __restrict__ hp, int hp_stride, // may be null
                              const float* __restrict__ b_ih,
                              const float* __restrict__ b_hh,
                              float* __restrict__ out, int out_stride) {
    long long idx = (long long)blockIdx.x * blockDim.x + threadIdx.x; // M*128
    int j = (int)(idx & 127);
    long long m = idx >> 7;
    const float* gir = gi + m * GDIM;
    float ir = gir[j]        + b_ih[j];
    float iz = gir[128 + j]  + b_ih[128 + j];
    float in_ = gir[256 + j] + b_ih[256 + j];
    float hr, hz, hn;
    if (gh) {
        const float* ghr = gh + m * GDIM;
        hr = ghr[j]       + b_hh[j];
        hz = ghr[128 + j] + b_hh[128 + j];
        hn = ghr[256 + j] + b_hh[256 + j];
    } else {
        hr = b_hh[j]; hz = b_hh[128 + j]; hn = b_hh[256 + j];
    }
    float r = sigmoidf_(ir + hr);
    float z = sigmoidf_(iz + hz);
    float n = tanhf(in_ + r * hn);
    float hv = hp ? hp[m * (long long)hp_stride + j] : 0.0f;
    out[m * (long long)out_stride + j] = (1.0f - z) * n + z * hv;
}

// ---------------- logits: gelu( hh . w_con + b_con ) ---------------------------
__global__ void logits_kernel(const float* __restrict__ hh,
                              const float* __restrict__ w_con,
                              const float* __restrict__ b_con,
                              float* __restrict__ logits) {
    long long gth = (long long)blockIdx.x * blockDim.x + threadIdx.x;
    long long warp = gth >> 5;
    int lane = (int)(gth & 31);
    const float* row = hh + warp * 256;
    float s = 0.0f;
    #pragma unroll
    for (int k = 0; k < 8; k++) s = fmaf(row[lane + k * 32], w_con[lane + k * 32], s);
    #pragma unroll
    for (int o = 16; o > 0; o >>= 1) s += __shfl_xor_sync(0xFFFFFFFFu, s, o);
    if (lane == 0) {
        float x = s + b_con[0];
        logits[warp] = 0.5f * x * (1.0f + erff(x * 0.70710678118654752440f));
    }
}

// ---------------- JAX threefry2x32 gumbel, PARTITIONABLE mode ------------------
// bits(i) = out0 ^ out1, (out0,out1) = threefry2x32(key=(0,42), x0=0, x1=i)
__device__ __forceinline__ void threefry2x32_dev(unsigned k0, unsigned k1,
                                                 unsigned& x0, unsigned& x1) {
    unsigned ks2 = k0 ^ k1 ^ 0x1BD11BDAu;
    x0 += k0; x1 += k1;
#define TFR(r) { x0 += x1; x1 = (x1 << (r)) | (x1 >> (32 - (r))); x1 ^= x0; }
#define TFG(a, b, c, d, A0, A1, INC) TFR(a) TFR(b) TFR(c) TFR(d) x0 += (A0); x1 += (A1) + (INC);
    TFG(13, 15, 26, 6,  k1,  ks2, 1u)
    TFG(17, 29, 16, 24, ks2, k0,  2u)
    TFG(13, 15, 26, 6,  k0,  k1,  3u)
    TFG(17, 29, 16, 24, k1,  ks2, 4u)
    TFG(13, 15, 26, 6,  ks2, k0,  5u)
#undef TFR
#undef TFG
}

__device__ __forceinline__ float bits_to_gumbel(unsigned bits) {
    float u = __uint_as_float((bits >> 9) | 0x3f800000u) - 1.0f;
    float v = fmaxf(u, 1.175494350822287508e-38f);
    return -logf(-logf(v));
}

__global__ void gumbel_kernel(float* __restrict__ g) {
    int i = blockIdx.x * blockDim.x + threadIdx.x;  // 0..255999 flat (E,B) index
    if (i >= MM) return;
    unsigned x0 = 0u, x1 = (unsigned)i;
    threefry2x32_dev(0u, 42u, x0, x1);
    g[i] = bits_to_gumbel(x0 ^ x1);
}

// ---------------- init / segment softmax / scatter -----------------------------
__global__ void init_kernel(float* __restrict__ out,
                            unsigned* __restrict__ mxh, unsigned* __restrict__ mxs,
                            float* __restrict__ sh, float* __restrict__ ss) {
    int i = blockIdx.x * blockDim.x + threadIdx.x;
    if (i < BB * NN * HH) out[i] = 0.0f;
    if (i < NN * BB) { mxh[i] = ENC_NEG_INF; mxs[i] = ENC_NEG_INF; sh[i] = 0.0f; ss[i] = 0.0f; }
}

__global__ void prep_kernel(const float* __restrict__ logits, const float* __restrict__ g,
                            const int* __restrict__ src,
                            float* __restrict__ av,
                            unsigned* __restrict__ mxh, unsigned* __restrict__ mxs) {
    int f = blockIdx.x * blockDim.x + threadIdx.x;   // f = e*B + b, 256000 total
    int e = f >> 1, b = f & 1;
    float l = logits[(size_t)b * EE + e];
    float a = (l + g[f]) / 0.1f;
    av[f] = a;
    int n2 = src[e] * BB + b;
    atomicMax(&mxh[n2], enc_f(a));
    atomicMax(&mxs[n2], enc_f(l));
}

__global__ void sum_kernel(const float* __restrict__ logits, const float* __restrict__ av,
                           const int* __restrict__ src,
                           const unsigned* __restrict__ mxh, const unsigned* __restrict__ mxs,
                           float* __restrict__ sh, float* __restrict__ ss) {
    int f = blockIdx.x * blockDim.x + threadIdx.x;
    int e = f >> 1, b = f & 1;
    int n2 = src[e] * BB + b;
    atomicAdd(&sh[n2], expf(av[f] - dec_f(mxh[n2])));
    atomicAdd(&ss[n2], expf(logits[(size_t)b * EE + e] - dec_f(mxs[n2])));
}

__global__ void scatter_kernel(const float* __restrict__ h,
                               const int* __restrict__ tgt, const int* __restrict__ src,
                               const float* __restrict__ logits, const float* __restrict__ av,
                               const unsigned* __restrict__ mxh, const unsigned* __restrict__ mxs,
                               const float* __restrict__ sh, const float* __restrict__ ss,
                               float* __restrict__ out) {
    int e = blockIdx.x;
    int j = threadIdx.x;
    int s = src[e], t = tgt[e];
    #pragma unroll
    for (int b = 0; b < BB; b++) {
        int n2 = s * BB + b;
        float a = av[e * BB + b];
        float l = logits[(size_t)b * EE + e];
        float w = (expf(a - dec_f(mxh[n2])) / sh[n2]) * (expf(l - dec_f(mxs[n2])) / ss[n2]);
        float hv = h[((size_t)b * NN + s) * HH + j];
        atomicAdd(&out[((size_t)b * NN + t) * HH + j], hv * w);
    }
}

// ---------------- host orchestration -------------------------------------------
extern "C" void kernel_launch(void* const* d_in, const int* in_sizes, int n_in,
                              void* d_out, int out_size) {
    static const int map_ins[20]   = {0,1,2,3,4,5,6,7,8,9,10,11,12,13,14,15,16,17,18,19};
    static const int map_alpha[20] = {10,9,17,13,6,2,16,12,5,1,19,15,8,4,18,14,7,3,11,0};
    const int* mp = (in_sizes[0] == BB * NN * HH) ? map_ins : map_alpha;

    const float* h   = (const float*)d_in[mp[0]];
    const int* ei    = (const int*)d_in[mp[1]];
    const int* tgt   = ei;            // edge_index[0]
    const int* src   = ei + EE;       // edge_index[1]
    const float* wih0f = (const float*)d_in[mp[2]];
    const float* whh0f = (const float*)d_in[mp[3]];
    const float* bih0f = (const float*)d_in[mp[4]];
    const float* bhh0f = (const float*)d_in[mp[5]];
    const float* wih0b = (const float*)d_in[mp[6]];
    const float* whh0b = (const float*)d_in[mp[7]];
    const float* bih0b = (const float*)d_in[mp[8]];
    const float* bhh0b = (const float*)d_in[mp[9]];
    const float* wih1f = (const float*)d_in[mp[10]];
    const float* bih1f = (const float*)d_in[mp[12]];
    const float* bhh1f = (const float*)d_in[mp[13]];
    const float* wih1b = (const float*)d_in[mp[14]];
    const float* whh1b = (const float*)d_in[mp[15]];
    const float* bih1b = (const float*)d_in[mp[16]];
    const float* bhh1b = (const float*)d_in[mp[17]];
    const float* wcon  = (const float*)d_in[mp[18]];
    const float* bcon  = (const float*)d_in[mp[19]];
    float* out = (float*)d_out;

    float *x0, *x1, *gi, *gh, *y0, *y1, *hhb, *hb1, *logits, *av, *gum;
    float *sh, *ss;
    unsigned *mxh, *mxs;
    cudaGetSymbolAddress((void**)&x0, g_x0);
    cudaGetSymbolAddress((void**)&x1, g_x1);
    cudaGetSymbolAddress((void**)&gi, g_gi);
    cudaGetSymbolAddress((void**)&gh, g_gh);
    cudaGetSymbolAddress((void**)&y0, g_y0);
    cudaGetSymbolAddress((void**)&y1, g_y1);
    cudaGetSymbolAddress((void**)&hhb, g_hh);
    cudaGetSymbolAddress((void**)&hb1, g_hb1);
    cudaGetSymbolAddress((void**)&logits, g_logits);
    cudaGetSymbolAddress((void**)&av, g_av);
    cudaGetSymbolAddress((void**)&gum, g_gum);
    cudaGetSymbolAddress((void**)&mxh, g_mxh);
    cudaGetSymbolAddress((void**)&mxs, g_mxs);
    cudaGetSymbolAddress((void**)&sh, g_sh);
    cudaGetSymbolAddress((void**)&ss, g_ss);

    dim3 gemmGrid(GDIM / BN, MM / BM);   // (6, 4000)
    const int PW_BLOCKS = (MM * 128) / 256;   // 128000

    // gather x0 (target), x1 (source)
    gather_kernel<<<(MM * 32) / 256, 256>>>((const float4*)h, tgt, src,
                                            (float4*)x0, (float4*)x1);

    // ---- layer 0 forward: f0 = cell(x0, 0) ; f1 = cell(x1, f0) ----
    sgemm_nt<<<gemmGrid, 128>>>(x0, 128, wih0f, 128, gi);
    gru_pointwise<<<PW_BLOCKS, 256>>>(gi, nullptr, nullptr, 0, bih0f, bhh0f, y0, 256);

    sgemm_nt<<<gemmGrid, 128>>>(x1, 128, wih0f, 128, gi);
    sgemm_nt<<<gemmGrid, 128>>>(y0, 256, whh0f, 128, gh);
    gru_pointwise<<<PW_BLOCKS, 256>>>(gi, gh, y0, 256, bih0f, bhh0f, y1, 256);

    // ---- layer 0 backward: b1 = cell(x1, 0) ; b0 = cell(x0, b1) ----
    sgemm_nt<<<gemmGrid, 128>>>(x1, 128, wih0b, 128, gi);
    gru_pointwise<<<PW_BLOCKS, 256>>>(gi, nullptr, nullptr, 0, bih0b, bhh0b, y1 + 128, 256);

    sgemm_nt<<<gemmGrid, 128>>>(x0, 128, wih0b, 128, gi);
    sgemm_nt<<<gemmGrid, 128>>>(y1 + 128, 256, whh0b, 128, gh);
    gru_pointwise<<<PW_BLOCKS, 256>>>(gi, gh, y1 + 128, 256, bih0b, bhh0b, y0 + 128, 256);

    // ---- layer 1: f0' = cellf(y0,0) ; b1' = cellb(y1,0) ; b0' = cellb(y0,b1')
    //      (f1' is never used downstream -> skipped)
    sgemm_nt<<<gemmGrid, 128>>>(y0, 256, wih1f, 256, gi);
    gru_pointwise<<<PW_BLOCKS, 256>>>(gi, nullptr, nullptr, 0, bih1f, bhh1f, hhb, 256);

    sgemm_nt<<<gemmGrid, 128>>>(y1, 256, wih1b, 256, gi);
    gru_pointwise<<<PW_BLOCKS, 256>>>(gi, nullptr, nullptr, 0, bih1b, bhh1b, hb1, 128);

    sgemm_nt<<<gemmGrid, 128>>>(y0, 256, wih1b, 256, gi);
    sgemm_nt<<<gemmGrid, 128>>>(hb1, 128, whh1b, 128, gh);
    gru_pointwise<<<PW_BLOCKS, 256>>>(gi, gh, hb1, 128, bih1b, bhh1b, hhb + 128, 256);

    // ---- logits, gumbel, segment softmaxes, weighted scatter ----
    logits_kernel<<<(MM * 32) / 256, 256>>>(hhb, wcon, bcon, logits);
    gumbel_kernel<<<(MM + 255) / 256, 256>>>(gum);
    init_kernel<<<(BB * NN * HH + 255) / 256, 256>>>(out, mxh, mxs, sh, ss);
    prep_kernel<<<MM / 256, 256>>>(logits, gum, src, av, mxh, mxs);
    sum_kernel<<<MM / 256, 256>>>(logits, av, src, mxh, mxs, sh, ss);
    scatter_kernel<<<EE, 128>>>(h, tgt, src, logits, av, mxh, mxs, sh, ss, out);
}

// round 5
// speedup vs baseline: 1.6481x; 1.6481x over previous
#include <cuda_runtime.h>
#include <cuda_bf16.h>
#include <math.h>
#include <stdint.h>

// Problem constants
#define BB 2
#define NN 10000
#define HH 128
#define EE 128000
#define MM (BB*EE)          // 256000 rows
#define GDIM 384            // 3*H

// ---------------- scratch (device globals; no runtime allocation) -------------
__device__ float g_x0[(size_t)MM*128];
__device__ float g_x1[(size_t)MM*128];
__device__ float g_gi[(size_t)MM*384];
__device__ float g_gh[(size_t)MM*384];
__device__ float g_y0[(size_t)MM*256];
__device__ float g_y1[(size_t)MM*256];
__device__ float g_hh[(size_t)MM*256];
__device__ float g_hb1[(size_t)MM*128];
__device__ float g_logits[MM];
__device__ float g_av[MM];
__device__ float g_gum[MM];
__device__ unsigned g_mxh[NN*BB];
__device__ unsigned g_mxs[NN*BB];
__device__ float g_sh[NN*BB];
__device__ float g_ss[NN*BB];

// ---------------- helpers -----------------------------------------------------
__device__ __forceinline__ unsigned enc_f(float x) {
    unsigned u = __float_as_uint(x);
    return (u & 0x80000000u) ? ~u : (u | 0x80000000u);
}
__device__ __forceinline__ float dec_f(unsigned v) {
    return (v & 0x80000000u) ? __uint_as_float(v ^ 0x80000000u) : __uint_as_float(~v);
}
#define ENC_NEG_INF 0x007FFFFFu

__device__ __forceinline__ float sigmoidf_(float x) { return 1.0f / (1.0f + expf(-x)); }

__device__ __forceinline__ uint32_t smem_u32(const void* p) {
    uint32_t a;
    asm("{ .reg .u64 t; cvta.to.shared.u64 t, %1; cvt.u32.u64 %0, t; }" : "=r"(a) : "l"(p));
    return a;
}

#define LDMX4(r0, r1, r2, r3, addr) \
    asm volatile("ldmatrix.sync.aligned.m8n8.x4.shared.b16 {%0,%1,%2,%3}, [%4];" \
                 : "=r"(r0), "=r"(r1), "=r"(r2), "=r"(r3) : "r"(addr))

#define MMA_BF16(c, a0, a1, a2, a3, b0, b1) \
    asm volatile("mma.sync.aligned.m16n8k16.row.col.f32.bf16.bf16.f32 " \
                 "{%0,%1,%2,%3}, {%4,%5,%6,%7}, {%8,%9}, {%0,%1,%2,%3};" \
                 : "+f"((c)[0]), "+f"((c)[1]), "+f"((c)[2]), "+f"((c)[3]) \
                 : "r"(a0), "r"(a1), "r"(a2), "r"(a3), "r"(b0), "r"(b1))

// bf16 hi/lo split: x ~= hi + lo with residual ~2^-18 * |x|
__device__ __forceinline__ void split_bf16(float x, __nv_bfloat16& hi, __nv_bfloat16& lo) {
    hi = __float2bfloat16_rn(x);
    lo = __float2bfloat16_rn(x - __bfloat162float(hi));
}

// ---------------- gather ------------------------------------------------------
__global__ void gather_kernel(const float4* __restrict__ h,
                              const int* __restrict__ tgt,
                              const int* __restrict__ src,
                              float4* __restrict__ x0, float4* __restrict__ x1) {
    long long idx = (long long)blockIdx.x * blockDim.x + threadIdx.x;
    int q = (int)(idx & 31);
    long long be = idx >> 5;
    int e = (int)(be % EE);
    int b = (int)(be / EE);
    int t = tgt[e], s = src[e];
    x0[be * 32 + q] = h[((long long)b * NN + t) * 32 + q];
    x1[be * 32 + q] = h[((long long)b * NN + s) * 32 + q];
}

// ---------------- bf16x3 HMMA GEMM: C[M x 384] = Act[M x K] * W^T --------------
// W is [384 x K] row-major (k-contiguous) -> NT layout, plain ldmatrix for both.
// CTA: 128 act rows x 128 weight rows. 8 warps: warp_m (4) x warp_n (2),
// warp tile 32 (M) x 64 (N). K chunked by 32 (two k16 steps).
#define SBF 40   // smem row stride in bf16 (80B): conflict-free ldmatrix

__global__ void __launch_bounds__(256) sgemm_mma(
        const float* __restrict__ Act, int ldb,
        const float* __restrict__ W, int K,
        float* __restrict__ C) {
    __shared__ __align__(16) __nv_bfloat16 sAh[128 * SBF];
    __shared__ __align__(16) __nv_bfloat16 sAl[128 * SBF];
    __shared__ __align__(16) __nv_bfloat16 sWh[128 * SBF];
    __shared__ __align__(16) __nv_bfloat16 sWl[128 * SBF];

    int tid = threadIdx.x;
    int lane = tid & 31;
    int wid = tid >> 5;
    int warp_m = wid & 3;      // 0..3 -> 32-row slice
    int warp_n = wid >> 2;     // 0..1 -> 64-col slice
    int rowBlk = blockIdx.y * 128;
    int colBlk = blockIdx.x * 128;

    uint32_t uAh = smem_u32(sAh), uAl = smem_u32(sAl);
    uint32_t uWh = smem_u32(sWh), uWl = smem_u32(sWl);

    float c[2][8][4];
    #pragma unroll
    for (int i = 0; i < 2; i++)
        #pragma unroll
        for (int j = 0; j < 8; j++)
            #pragma unroll
            for (int q = 0; q < 4; q++) c[i][j][q] = 0.0f;

    // ldmatrix source addresses (element offsets within tile, bf16 units)
    // A frag (16x16): row = lane&15, colgrp = (lane>>4)*8
    int a_r = lane & 15, a_c = (lane >> 4) << 3;
    // B frag (2 n-tiles x k16): nrow = (lane&7) + ((lane>>4)<<3), kcol = ((lane>>3)&1)*8
    int b_r = (lane & 7) + ((lane >> 4) << 3);
    int b_c = ((lane >> 3) & 1) << 3;

    for (int kc = 0; kc < K; kc += 32) {
        // ---- load fp32, split to bf16 hi/lo, store to smem ----
        #pragma unroll
        for (int t = 0; t < 4; t++) {
            int idx = tid + t * 256;       // 0..1023
            int r = idx >> 3, c4 = (idx & 7) * 4;
            float4 va = *(const float4*)(Act + (size_t)(rowBlk + r) * ldb + kc + c4);
            float4 vw = *(const float4*)(W + (size_t)(colBlk + r) * K + kc + c4);
            int off = r * SBF + c4;
            __nv_bfloat16 h0, l0, h1, l1, h2, l2, h3, l3;
            split_bf16(va.x, h0, l0); split_bf16(va.y, h1, l1);
            split_bf16(va.z, h2, l2); split_bf16(va.w, h3, l3);
            sAh[off] = h0; sAh[off+1] = h1; sAh[off+2] = h2; sAh[off+3] = h3;
            sAl[off] = l0; sAl[off+1] = l1; sAl[off+2] = l2; sAl[off+3] = l3;
            split_bf16(vw.x, h0, l0); split_bf16(vw.y, h1, l1);
            split_bf16(vw.z, h2, l2); split_bf16(vw.w, h3, l3);
            sWh[off] = h0; sWh[off+1] = h1; sWh[off+2] = h2; sWh[off+3] = h3;
            sWl[off] = l0; sWl[off+1] = l1; sWl[off+2] = l2; sWl[off+3] = l3;
        }
        __syncthreads();

        #pragma unroll
        for (int ks = 0; ks < 2; ks++) {
            // A fragments: 2 m-tiles, hi and lo
            uint32_t ah[2][4], al[2][4];
            #pragma unroll
            for (int mt = 0; mt < 2; mt++) {
                uint32_t eoff = (uint32_t)((warp_m * 32 + mt * 16 + a_r) * SBF
                                           + ks * 16 + a_c) * 2;
                LDMX4(ah[mt][0], ah[mt][1], ah[mt][2], ah[mt][3], uAh + eoff);
                LDMX4(al[mt][0], al[mt][1], al[mt][2], al[mt][3], uAl + eoff);
            }
            #pragma unroll
            for (int np = 0; np < 4; np++) {       // 4 pairs of n-tiles (16 cols each)
                uint32_t bh[4], bl[4];
                uint32_t eoff = (uint32_t)((warp_n * 64 + np * 16 + b_r) * SBF
                                           + ks * 16 + b_c) * 2;
                LDMX4(bh[0], bh[1], bh[2], bh[3], uWh + eoff);
                LDMX4(bl[0], bl[1], bl[2], bl[3], uWl + eoff);
                #pragma unroll
                for (int mt = 0; mt < 2; mt++) {
                    float* c0 = c[mt][np * 2];
                    float* c1 = c[mt][np * 2 + 1];
                    MMA_BF16(c0, ah[mt][0], ah[mt][1], ah[mt][2], ah[mt][3], bh[0], bh[1]);
                    MMA_BF16(c0, ah[mt][0], ah[mt][1], ah[mt][2], ah[mt][3], bl[0], bl[1]);
                    MMA_BF16(c0, al[mt][0], al[mt][1], al[mt][2], al[mt][3], bh[0], bh[1]);
                    MMA_BF16(c1, ah[mt][0], ah[mt][1], ah[mt][2], ah[mt][3], bh[2], bh[3]);
                    MMA_BF16(c1, ah[mt][0], ah[mt][1], ah[mt][2], ah[mt][3], bl[2], bl[3]);
                    MMA_BF16(c1, al[mt][0], al[mt][1], al[mt][2], al[mt][3], bh[2], bh[3]);
                }
            }
        }
        __syncthreads();
    }

    // ---- epilogue: accum layout c0,c1 -> (row, col..col+1), c2,c3 -> row+8 ----
    #pragma unroll
    for (int mt = 0; mt < 2; mt++) {
        int r = rowBlk + warp_m * 32 + mt * 16 + (lane >> 2);
        #pragma unroll
        for (int nt = 0; nt < 8; nt++) {
            int col = colBlk + warp_n * 64 + nt * 8 + (lane & 3) * 2;
            *(float2*)(C + (size_t)r * GDIM + col) =
                make_float2(c[mt][nt][0], c[mt][nt][1]);
            *(float2*)(C + (size_t)(r + 8) * GDIM + col) =
                make_float2(c[mt][nt][2], c[mt][nt][3]);
        }
    }
}

// ---------------- GRU pointwise ------------------------------------------------
__global__ void gru_pointwise(const float* __restrict__ gi,
                              const float* __restrict__ gh,
                              const float* __restrict__ hp, int hp_stride,
                              const float* __restrict__ b_ih,
                              const float* __restrict__ b_hh,
                              float* __restrict__ out, int out_stride) {
    long long idx = (long long)blockIdx.x * blockDim.x + threadIdx.x;
    int j = (int)(idx & 127);
    long long m = idx >> 7;
    const float* gir = gi + m * GDIM;
    float ir = gir[j]        + b_ih[j];
    float iz = gir[128 + j]  + b_ih[128 + j];
    float in_ = gir[256 + j] + b_ih[256 + j];
    float hr, hz, hn;
    if (gh) {
        const float* ghr = gh + m * GDIM;
        hr = ghr[j]       + b_hh[j];
        hz = ghr[128 + j] + b_hh[128 + j];
        hn = ghr[256 + j] + b_hh[256 + j];
    } else {
        hr = b_hh[j]; hz = b_hh[128 + j]; hn = b_hh[256 + j];
    }
    float r = sigmoidf_(ir + hr);
    float z = sigmoidf_(iz + hz);
    float n = tanhf(in_ + r * hn);
    float hv = hp ? hp[m * (long long)hp_stride + j] : 0.0f;
    out[m * (long long)out_stride + j] = (1.0f - z) * n + z * hv;
}

// ---------------- logits ---------------------------------------------------------
__global__ void logits_kernel(const float* __restrict__ hh,
                              const float* __restrict__ w_con,
                              const float* __restrict__ b_con,
                              float* __restrict__ logits) {
    long long gth = (long long)blockIdx.x * blockDim.x + threadIdx.x;
    long long warp = gth >> 5;
    int lane = (int)(gth & 31);
    const float* row = hh + warp * 256;
    float s = 0.0f;
    #pragma unroll
    for (int k = 0; k < 8; k++) s = fmaf(row[lane + k * 32], w_con[lane + k * 32], s);
    #pragma unroll
    for (int o = 16; o > 0; o >>= 1) s += __shfl_xor_sync(0xFFFFFFFFu, s, o);
    if (lane == 0) {
        float x = s + b_con[0];
        logits[warp] = 0.5f * x * (1.0f + erff(x * 0.70710678118654752440f));
    }
}

// ---------------- JAX threefry2x32 gumbel, partitionable mode -------------------
__device__ __forceinline__ void threefry2x32_dev(unsigned k0, unsigned k1,
                                                 unsigned& x0, unsigned& x1) {
    unsigned ks2 = k0 ^ k1 ^ 0x1BD11BDAu;
    x0 += k0; x1 += k1;
#define TFR(r) { x0 += x1; x1 = (x1 << (r)) | (x1 >> (32 - (r))); x1 ^= x0; }
#define TFG(a, b, c, d, A0, A1, INC) TFR(a) TFR(b) TFR(c) TFR(d) x0 += (A0); x1 += (A1) + (INC);
    TFG(13, 15, 26, 6,  k1,  ks2, 1u)
    TFG(17, 29, 16, 24, ks2, k0,  2u)
    TFG(13, 15, 26, 6,  k0,  k1,  3u)
    TFG(17, 29, 16, 24, k1,  ks2, 4u)
    TFG(13, 15, 26, 6,  ks2, k0,  5u)
#undef TFR
#undef TFG
}

__device__ __forceinline__ float bits_to_gumbel(unsigned bits) {
    float u = __uint_as_float((bits >> 9) | 0x3f800000u) - 1.0f;
    float v = fmaxf(u, 1.175494350822287508e-38f);
    return -logf(-logf(v));
}

__global__ void gumbel_kernel(float* __restrict__ g) {
    int i = blockIdx.x * blockDim.x + threadIdx.x;
    if (i >= MM) return;
    unsigned x0 = 0u, x1 = (unsigned)i;
    threefry2x32_dev(0u, 42u, x0, x1);
    g[i] = bits_to_gumbel(x0 ^ x1);
}

// ---------------- init / segment softmax / scatter -------------------------------
__global__ void init_kernel(float* __restrict__ out,
                            unsigned* __restrict__ mxh, unsigned* __restrict__ mxs,
                            float* __restrict__ sh, float* __restrict__ ss) {
    int i = blockIdx.x * blockDim.x + threadIdx.x;
    if (i < BB * NN * HH) out[i] = 0.0f;
    if (i < NN * BB) { mxh[i] = ENC_NEG_INF; mxs[i] = ENC_NEG_INF; sh[i] = 0.0f; ss[i] = 0.0f; }
}

__global__ void prep_kernel(const float* __restrict__ logits, const float* __restrict__ g,
                            const int* __restrict__ src,
                            float* __restrict__ av,
                            unsigned* __restrict__ mxh, unsigned* __restrict__ mxs) {
    int f = blockIdx.x * blockDim.x + threadIdx.x;
    int e = f >> 1, b = f & 1;
    float l = logits[(size_t)b * EE + e];
    float a = (l + g[f]) / 0.1f;
    av[f] = a;
    int n2 = src[e] * BB + b;
    atomicMax(&mxh[n2], enc_f(a));
    atomicMax(&mxs[n2], enc_f(l));
}

__global__ void sum_kernel(const float* __restrict__ logits, const float* __restrict__ av,
                           const int* __restrict__ src,
                           const unsigned* __restrict__ mxh, const unsigned* __restrict__ mxs,
                           float* __restrict__ sh, float* __restrict__ ss) {
    int f = blockIdx.x * blockDim.x + threadIdx.x;
    int e = f >> 1, b = f & 1;
    int n2 = src[e] * BB + b;
    atomicAdd(&sh[n2], expf(av[f] - dec_f(mxh[n2])));
    atomicAdd(&ss[n2], expf(logits[(size_t)b * EE + e] - dec_f(mxs[n2])));
}

__global__ void scatter_kernel(const float* __restrict__ h,
                               const int* __restrict__ tgt, const int* __restrict__ src,
                               const float* __restrict__ logits, const float* __restrict__ av,
                               const unsigned* __restrict__ mxh, const unsigned* __restrict__ mxs,
                               const float* __restrict__ sh, const float* __restrict__ ss,
                               float* __restrict__ out) {
    int e = blockIdx.x;
    int j = threadIdx.x;
    int s = src[e], t = tgt[e];
    #pragma unroll
    for (int b = 0; b < BB; b++) {
        int n2 = s * BB + b;
        float a = av[e * BB + b];
        float l = logits[(size_t)b * EE + e];
        float w = (expf(a - dec_f(mxh[n2])) / sh[n2]) * (expf(l - dec_f(mxs[n2])) / ss[n2]);
        float hv = h[((size_t)b * NN + s) * HH + j];
        atomicAdd(&out[((size_t)b * NN + t) * HH + j], hv * w);
    }
}

// ---------------- host orchestration ---------------------------------------------
extern "C" void kernel_launch(void* const* d_in, const int* in_sizes, int n_in,
                              void* d_out, int out_size) {
    static const int map_ins[20]   = {0,1,2,3,4,5,6,7,8,9,10,11,12,13,14,15,16,17,18,19};
    static const int map_alpha[20] = {10,9,17,13,6,2,16,12,5,1,19,15,8,4,18,14,7,3,11,0};
    const int* mp = (in_sizes[0] == BB * NN * HH) ? map_ins : map_alpha;

    const float* h   = (const float*)d_in[mp[0]];
    const int* ei    = (const int*)d_in[mp[1]];
    const int* tgt   = ei;
    const int* src   = ei + EE;
    const float* wih0f = (const float*)d_in[mp[2]];
    const float* whh0f = (const float*)d_in[mp[3]];
    const float* bih0f = (const float*)d_in[mp[4]];
    const float* bhh0f = (const float*)d_in[mp[5]];
    const float* wih0b = (const float*)d_in[mp[6]];
    const float* whh0b = (const float*)d_in[mp[7]];
    const float* bih0b = (const float*)d_in[mp[8]];
    const float* bhh0b = (const float*)d_in[mp[9]];
    const float* wih1f = (const float*)d_in[mp[10]];
    const float* bih1f = (const float*)d_in[mp[12]];
    const float* bhh1f = (const float*)d_in[mp[13]];
    const float* wih1b = (const float*)d_in[mp[14]];
    const float* whh1b = (const float*)d_in[mp[15]];
    const float* bih1b = (const float*)d_in[mp[16]];
    const float* bhh1b = (const float*)d_in[mp[17]];
    const float* wcon  = (const float*)d_in[mp[18]];
    const float* bcon  = (const float*)d_in[mp[19]];
    float* out = (float*)d_out;

    float *x0, *x1, *gi, *gh, *y0, *y1, *hhb, *hb1, *logits, *av, *gum;
    float *sh, *ss;
    unsigned *mxh, *mxs;
    cudaGetSymbolAddress((void**)&x0, g_x0);
    cudaGetSymbolAddress((void**)&x1, g_x1);
    cudaGetSymbolAddress((void**)&gi, g_gi);
    cudaGetSymbolAddress((void**)&gh, g_gh);
    cudaGetSymbolAddress((void**)&y0, g_y0);
    cudaGetSymbolAddress((void**)&y1, g_y1);
    cudaGetSymbolAddress((void**)&hhb, g_hh);
    cudaGetSymbolAddress((void**)&hb1, g_hb1);
    cudaGetSymbolAddress((void**)&logits, g_logits);
    cudaGetSymbolAddress((void**)&av, g_av);
    cudaGetSymbolAddress((void**)&gum, g_gum);
    cudaGetSymbolAddress((void**)&mxh, g_mxh);
    cudaGetSymbolAddress((void**)&mxs, g_mxs);
    cudaGetSymbolAddress((void**)&sh, g_sh);
    cudaGetSymbolAddress((void**)&ss, g_ss);

    dim3 gemmGrid(3, 2000);                  // 384/128 cols x 256000/128 rows
    const int PW_BLOCKS = (MM * 128) / 256;  // 128000

    gather_kernel<<<(MM * 32) / 256, 256>>>((const float4*)h, tgt, src,
                                            (float4*)x0, (float4*)x1);

    // ---- layer 0 forward: f0 = cell(x0, 0) ; f1 = cell(x1, f0) ----
    sgemm_mma<<<gemmGrid, 256>>>(x0, 128, wih0f, 128, gi);
    gru_pointwise<<<PW_BLOCKS, 256>>>(gi, nullptr, nullptr, 0, bih0f, bhh0f, y0, 256);

    sgemm_mma<<<gemmGrid, 256>>>(x1, 128, wih0f, 128, gi);
    sgemm_mma<<<gemmGrid, 256>>>(y0, 256, whh0f, 128, gh);
    gru_pointwise<<<PW_BLOCKS, 256>>>(gi, gh, y0, 256, bih0f, bhh0f, y1, 256);

    // ---- layer 0 backward: b1 = cell(x1, 0) ; b0 = cell(x0, b1) ----
    sgemm_mma<<<gemmGrid, 256>>>(x1, 128, wih0b, 128, gi);
    gru_pointwise<<<PW_BLOCKS, 256>>>(gi, nullptr, nullptr, 0, bih0b, bhh0b, y1 + 128, 256);

    sgemm_mma<<<gemmGrid, 256>>>(x0, 128, wih0b, 128, gi);
    sgemm_mma<<<gemmGrid, 256>>>(y1 + 128, 256, whh0b, 128, gh);
    gru_pointwise<<<PW_BLOCKS, 256>>>(gi, gh, y1 + 128, 256, bih0b, bhh0b, y0 + 128, 256);

    // ---- layer 1: f0' = cellf(y0,0) ; b1' = cellb(y1,0) ; b0' = cellb(y0,b1') ----
    sgemm_mma<<<gemmGrid, 256>>>(y0, 256, wih1f, 256, gi);
    gru_pointwise<<<PW_BLOCKS, 256>>>(gi, nullptr, nullptr, 0, bih1f, bhh1f, hhb, 256);

    sgemm_mma<<<gemmGrid, 256>>>(y1, 256, wih1b, 256, gi);
    gru_pointwise<<<PW_BLOCKS, 256>>>(gi, nullptr, nullptr, 0, bih1b, bhh1b, hb1, 128);

    sgemm_mma<<<gemmGrid, 256>>>(y0, 256, wih1b, 256, gi);
    sgemm_mma<<<gemmGrid, 256>>>(hb1, 128, whh1b, 128, gh);
    gru_pointwise<<<PW_BLOCKS, 256>>>(gi, gh, hb1, 128, bih1b, bhh1b, hhb + 128, 256);

    // ---- logits, gumbel, segment softmaxes, weighted scatter ----
    logits_kernel<<<(MM * 32) / 256, 256>>>(hhb, wcon, bcon, logits);
    gumbel_kernel<<<(MM + 255) / 256, 256>>>(gum);
    init_kernel<<<(BB * NN * HH + 255) / 256, 256>>>(out, mxh, mxs, sh, ss);
    prep_kernel<<<MM / 256, 256>>>(logits, gum, src, av, mxh, mxs);
    sum_kernel<<<MM / 256, 256>>>(logits, av, src, mxh, mxs, sh, ss);
    scatter_kernel<<<EE, 128>>>(h, tgt, src, logits, av, mxh, mxs, sh, ss, out);
}

// round 6
// speedup vs baseline: 2.1758x; 1.3201x over previous
#include <cuda_runtime.h>
#include <cuda_bf16.h>
#include <math.h>
#include <stdint.h>

// Problem constants
#define BB 2
#define NN 10000
#define HH 128
#define EE 128000
#define MM (BB*EE)          // 256000 rows
#define GDIM 384            // 3*H

// ---------------- scratch (device globals; no runtime allocation) -------------
__device__ float g_gi[(size_t)MM*384];
__device__ float g_gh[(size_t)MM*384];
__device__ float g_y0[(size_t)MM*256];
__device__ float g_y1[(size_t)MM*256];
__device__ float g_hh[(size_t)MM*256];
__device__ float g_hb1[(size_t)MM*128];
__device__ float g_logits[MM];
__device__ float g_av[MM];
__device__ float g_gum[MM];
__device__ unsigned g_mxh[NN*BB];
__device__ unsigned g_mxs[NN*BB];
__device__ float g_sh[NN*BB];
__device__ float g_ss[NN*BB];

// bf16 hi/lo activation buffers
__device__ __nv_bfloat16 g_x0h[(size_t)MM*128], g_x0l[(size_t)MM*128];
__device__ __nv_bfloat16 g_x1h[(size_t)MM*128], g_x1l[(size_t)MM*128];
__device__ __nv_bfloat16 g_y0h[(size_t)MM*256], g_y0l[(size_t)MM*256];
__device__ __nv_bfloat16 g_y1h[(size_t)MM*256], g_y1l[(size_t)MM*256];
__device__ __nv_bfloat16 g_hb1h[(size_t)MM*128], g_hb1l[(size_t)MM*128];

// packed pre-split weights: layout [cb][kc][r(128)][c(32)]
// offsets (elements): wih0f 0, whh0f 49152, wih0b 98304, whh0b 147456,
//                     whh1b 196608, wih1f 245760 (K=256), wih1b 344064 (K=256)
#define WPK_TOTAL 442368
__device__ __nv_bfloat16 g_wpk_h[WPK_TOTAL];
__device__ __nv_bfloat16 g_wpk_l[WPK_TOTAL];

// ---------------- helpers -----------------------------------------------------
__device__ __forceinline__ unsigned enc_f(float x) {
    unsigned u = __float_as_uint(x);
    return (u & 0x80000000u) ? ~u : (u | 0x80000000u);
}
__device__ __forceinline__ float dec_f(unsigned v) {
    return (v & 0x80000000u) ? __uint_as_float(v ^ 0x80000000u) : __uint_as_float(~v);
}
#define ENC_NEG_INF 0x007FFFFFu

__device__ __forceinline__ float sigmoidf_(float x) { return 1.0f / (1.0f + expf(-x)); }

__device__ __forceinline__ uint32_t smem_u32(const void* p) {
    uint32_t a;
    asm("{ .reg .u64 t; cvta.to.shared.u64 t, %1; cvt.u32.u64 %0, t; }" : "=r"(a) : "l"(p));
    return a;
}

#define LDMX4(r0, r1, r2, r3, addr) \
    asm volatile("ldmatrix.sync.aligned.m8n8.x4.shared.b16 {%0,%1,%2,%3}, [%4];" \
                 : "=r"(r0), "=r"(r1), "=r"(r2), "=r"(r3) : "r"(addr))

#define MMA_BF16(c, a0, a1, a2, a3, b0, b1) \
    asm volatile("mma.sync.aligned.m16n8k16.row.col.f32.bf16.bf16.f32 " \
                 "{%0,%1,%2,%3}, {%4,%5,%6,%7}, {%8,%9}, {%0,%1,%2,%3};" \
                 : "+f"((c)[0]), "+f"((c)[1]), "+f"((c)[2]), "+f"((c)[3]) \
                 : "r"(a0), "r"(a1), "r"(a2), "r"(a3), "r"(b0), "r"(b1))

#define CPA16(dst, src) \
    asm volatile("cp.async.cg.shared.global [%0], [%1], 16;" :: "r"(dst), "l"(src))
#define CPA_COMMIT() asm volatile("cp.async.commit_group;" ::: "memory")
#define CPA_WAIT1() asm volatile("cp.async.wait_group 1;" ::: "memory")

__device__ __forceinline__ void split_bf16(float x, __nv_bfloat16& hi, __nv_bfloat16& lo) {
    hi = __float2bfloat16_rn(x);
    lo = __float2bfloat16_rn(x - __bfloat162float(hi));
}

// ---------------- weight pre-split/pack ----------------------------------------
__global__ void pack_w(const float* __restrict__ W, int K,
                       __nv_bfloat16* __restrict__ outh,
                       __nv_bfloat16* __restrict__ outl) {
    int idx = blockIdx.x * blockDim.x + threadIdx.x;  // cb*nkc*4096
    int nkc = K >> 5;
    int c = idx & 31;
    int r = (idx >> 5) & 127;
    int kcb = idx >> 12;        // cb*nkc + kc
    int kc = kcb % nkc, cb = kcb / nkc;
    if (cb >= 3) return;
    float v = W[(size_t)(cb * 128 + r) * K + kc * 32 + c];
    __nv_bfloat16 hi, lo; split_bf16(v, hi, lo);
    outh[idx] = hi; outl[idx] = lo;
}

// ---------------- gather (writes bf16 hi/lo) ------------------------------------
__global__ void gather_kernel(const float4* __restrict__ h,
                              const int* __restrict__ tgt,
                              const int* __restrict__ src,
                              __nv_bfloat16* __restrict__ x0h, __nv_bfloat16* __restrict__ x0l,
                              __nv_bfloat16* __restrict__ x1h, __nv_bfloat16* __restrict__ x1l) {
    long long idx = (long long)blockIdx.x * blockDim.x + threadIdx.x; // M*32
    int q = (int)(idx & 31);
    long long be = idx >> 5;
    int e = (int)(be % EE);
    int b = (int)(be / EE);
    int t = tgt[e], s = src[e];
    float4 vt = h[((long long)b * NN + t) * 32 + q];
    float4 vs = h[((long long)b * NN + s) * 32 + q];
    __nv_bfloat16 hh_[4], ll_[4];
    long long o = be * 128 + q * 4;
    split_bf16(vt.x, hh_[0], ll_[0]); split_bf16(vt.y, hh_[1], ll_[1]);
    split_bf16(vt.z, hh_[2], ll_[2]); split_bf16(vt.w, hh_[3], ll_[3]);
    *(ulonglong1*)(x0h + o) = *(ulonglong1*)hh_;
    *(ulonglong1*)(x0l + o) = *(ulonglong1*)ll_;
    split_bf16(vs.x, hh_[0], ll_[0]); split_bf16(vs.y, hh_[1], ll_[1]);
    split_bf16(vs.z, hh_[2], ll_[2]); split_bf16(vs.w, hh_[3], ll_[3]);
    *(ulonglong1*)(x1h + o) = *(ulonglong1*)hh_;
    *(ulonglong1*)(x1l + o) = *(ulonglong1*)ll_;
}

// ---------------- bf16x3 HMMA GEMM, cp.async double-buffered --------------------
// C[M x 384] = Act[M x K] * W^T.  Act given pre-split bf16 hi/lo (row stride lda).
// Weights pre-split+packed per (cb,kc) 128x32 chunk.
// CTA: 128 act rows x 128 weight rows; 8 warps (4 m x 2 n), warp tile 32x64.
#define SBF 40                      // smem row stride in bf16 (80 B)
#define TILE_B (128 * SBF * 2)      // 10240 B per tile
#define STAGE_B (4 * TILE_B)        // 40960 B per stage

__global__ void __launch_bounds__(256) sgemm_mma(
        const __nv_bfloat16* __restrict__ Ah, const __nv_bfloat16* __restrict__ Al,
        int lda,
        const __nv_bfloat16* __restrict__ Wh, const __nv_bfloat16* __restrict__ Wl,
        int nkc,
        float* __restrict__ C) {
    extern __shared__ __align__(16) char smem[];
    uint32_t sb = smem_u32(smem);

    int tid = threadIdx.x;
    int lane = tid & 31;
    int wid = tid >> 5;
    int warp_m = wid & 3;
    int warp_n = wid >> 2;
    int rowBlk = blockIdx.y * 128;
    int cb = blockIdx.x;

    float c[2][8][4];
    #pragma unroll
    for (int i = 0; i < 2; i++)
        #pragma unroll
        for (int j = 0; j < 8; j++)
            #pragma unroll
            for (int q = 0; q < 4; q++) c[i][j][q] = 0.0f;

    // per-thread cp.async assignments: 8 chunks of 16B
    // id = tid + q*256 in 0..2047 ; tile = id>>9 ; r = (id&511)>>2 ; c16 = id&3
    // issue loads for chunk kc into stage buffer s
    auto issue = [&](int kc, int s) {
        #pragma unroll
        for (int q = 0; q < 8; q++) {
            int id = tid + q * 256;
            int tile = id >> 9;
            int rem = id & 511;
            int r = rem >> 2, c16 = rem & 3;
            uint32_t dst = sb + s * STAGE_B + tile * TILE_B + r * (SBF * 2) + c16 * 16;
            const __nv_bfloat16* src;
            if (tile == 0)
                src = Ah + (size_t)(rowBlk + r) * lda + kc * 32 + c16 * 8;
            else if (tile == 1)
                src = Al + (size_t)(rowBlk + r) * lda + kc * 32 + c16 * 8;
            else if (tile == 2)
                src = Wh + ((size_t)(cb * nkc + kc) << 12) + r * 32 + c16 * 8;
            else
                src = Wl + ((size_t)(cb * nkc + kc) << 12) + r * 32 + c16 * 8;
            CPA16(dst, src);
        }
    };

    // ldmatrix element offsets
    int a_r = lane & 15, a_c = (lane >> 4) << 3;
    int b_r = (lane & 7) + ((lane >> 4) << 3);
    int b_c = ((lane >> 3) & 1) << 3;

    issue(0, 0);
    CPA_COMMIT();

    for (int kc = 0; kc < nkc; kc++) {
        if (kc + 1 < nkc) issue(kc + 1, (kc + 1) & 1);
        CPA_COMMIT();
        CPA_WAIT1();
        __syncthreads();

        uint32_t st = sb + (kc & 1) * STAGE_B;
        uint32_t uAh = st, uAl = st + TILE_B, uWh = st + 2 * TILE_B, uWl = st + 3 * TILE_B;

        #pragma unroll
        for (int ks = 0; ks < 2; ks++) {
            uint32_t ah[2][4], al[2][4];
            #pragma unroll
            for (int mt = 0; mt < 2; mt++) {
                uint32_t eoff = (uint32_t)((warp_m * 32 + mt * 16 + a_r) * SBF
                                           + ks * 16 + a_c) * 2;
                LDMX4(ah[mt][0], ah[mt][1], ah[mt][2], ah[mt][3], uAh + eoff);
                LDMX4(al[mt][0], al[mt][1], al[mt][2], al[mt][3], uAl + eoff);
            }
            #pragma unroll
            for (int np = 0; np < 4; np++) {
                uint32_t bh[4], bl[4];
                uint32_t eoff = (uint32_t)((warp_n * 64 + np * 16 + b_r) * SBF
                                           + ks * 16 + b_c) * 2;
                LDMX4(bh[0], bh[1], bh[2], bh[3], uWh + eoff);
                LDMX4(bl[0], bl[1], bl[2], bl[3], uWl + eoff);
                #pragma unroll
                for (int mt = 0; mt < 2; mt++) {
                    float* c0 = c[mt][np * 2];
                    float* c1 = c[mt][np * 2 + 1];
                    MMA_BF16(c0, ah[mt][0], ah[mt][1], ah[mt][2], ah[mt][3], bh[0], bh[1]);
                    MMA_BF16(c0, ah[mt][0], ah[mt][1], ah[mt][2], ah[mt][3], bl[0], bl[1]);
                    MMA_BF16(c0, al[mt][0], al[mt][1], al[mt][2], al[mt][3], bh[0], bh[1]);
                    MMA_BF16(c1, ah[mt][0], ah[mt][1], ah[mt][2], ah[mt][3], bh[2], bh[3]);
                    MMA_BF16(c1, ah[mt][0], ah[mt][1], ah[mt][2], ah[mt][3], bl[2], bl[3]);
                    MMA_BF16(c1, al[mt][0], al[mt][1], al[mt][2], al[mt][3], bh[2], bh[3]);
                }
            }
        }
        __syncthreads();
    }

    int colBlk = cb * 128;
    #pragma unroll
    for (int mt = 0; mt < 2; mt++) {
        int r = rowBlk + warp_m * 32 + mt * 16 + (lane >> 2);
        #pragma unroll
        for (int nt = 0; nt < 8; nt++) {
            int col = colBlk + warp_n * 64 + nt * 8 + (lane & 3) * 2;
            *(float2*)(C + (size_t)r * GDIM + col) =
                make_float2(c[mt][nt][0], c[mt][nt][1]);
            *(float2*)(C + (size_t)(r + 8) * GDIM + col) =
                make_float2(c[mt][nt][2], c[mt][nt][3]);
        }
    }
}

// ---------------- GRU pointwise (optionally emits bf16 hi/lo) -------------------
__global__ void gru_pointwise(const float* __restrict__ gi,
                              const float* __restrict__ gh,
                              const float* __restrict__ hp, int hp_stride,
                              const float* __restrict__ b_ih,
                              const float* __restrict__ b_hh,
                              float* __restrict__ out, int out_stride,
                              __nv_bfloat16* __restrict__ outh,
                              __nv_bfloat16* __restrict__ outl, int bf_stride) {
    long long idx = (long long)blockIdx.x * blockDim.x + threadIdx.x;
    int j = (int)(idx & 127);
    long long m = idx >> 7;
    const float* gir = gi + m * GDIM;
    float ir = gir[j]        + b_ih[j];
    float iz = gir[128 + j]  + b_ih[128 + j];
    float in_ = gir[256 + j] + b_ih[256 + j];
    float hr, hz, hn;
    if (gh) {
        const float* ghr = gh + m * GDIM;
        hr = ghr[j]       + b_hh[j];
        hz = ghr[128 + j] + b_hh[128 + j];
        hn = ghr[256 + j] + b_hh[256 + j];
    } else {
        hr = b_hh[j]; hz = b_hh[128 + j]; hn = b_hh[256 + j];
    }
    float r = sigmoidf_(ir + hr);
    float z = sigmoidf_(iz + hz);
    float n = tanhf(in_ + r * hn);
    float hv = hp ? hp[m * (long long)hp_stride + j] : 0.0f;
    float o = (1.0f - z) * n + z * hv;
    out[m * (long long)out_stride + j] = o;
    if (outh) {
        __nv_bfloat16 hi, lo; split_bf16(o, hi, lo);
        outh[m * (long long)bf_stride + j] = hi;
        outl[m * (long long)bf_stride + j] = lo;
    }
}

// ---------------- logits ---------------------------------------------------------
__global__ void logits_kernel(const float* __restrict__ hh,
                              const float* __restrict__ w_con,
                              const float* __restrict__ b_con,
                              float* __restrict__ logits) {
    long long gth = (long long)blockIdx.x * blockDim.x + threadIdx.x;
    long long warp = gth >> 5;
    int lane = (int)(gth & 31);
    const float* row = hh + warp * 256;
    float s = 0.0f;
    #pragma unroll
    for (int k = 0; k < 8; k++) s = fmaf(row[lane + k * 32], w_con[lane + k * 32], s);
    #pragma unroll
    for (int o = 16; o > 0; o >>= 1) s += __shfl_xor_sync(0xFFFFFFFFu, s, o);
    if (lane == 0) {
        float x = s + b_con[0];
        logits[warp] = 0.5f * x * (1.0f + erff(x * 0.70710678118654752440f));
    }
}

// ---------------- JAX threefry2x32 gumbel, partitionable mode -------------------
__device__ __forceinline__ void threefry2x32_dev(unsigned k0, unsigned k1,
                                                 unsigned& x0, unsigned& x1) {
    unsigned ks2 = k0 ^ k1 ^ 0x1BD11BDAu;
    x0 += k0; x1 += k1;
#define TFR(r) { x0 += x1; x1 = (x1 << (r)) | (x1 >> (32 - (r))); x1 ^= x0; }
#define TFG(a, b, c, d, A0, A1, INC) TFR(a) TFR(b) TFR(c) TFR(d) x0 += (A0); x1 += (A1) + (INC);
    TFG(13, 15, 26, 6,  k1,  ks2, 1u)
    TFG(17, 29, 16, 24, ks2, k0,  2u)
    TFG(13, 15, 26, 6,  k0,  k1,  3u)
    TFG(17, 29, 16, 24, k1,  ks2, 4u)
    TFG(13, 15, 26, 6,  ks2, k0,  5u)
#undef TFR
#undef TFG
}

__device__ __forceinline__ float bits_to_gumbel(unsigned bits) {
    float u = __uint_as_float((bits >> 9) | 0x3f800000u) - 1.0f;
    float v = fmaxf(u, 1.175494350822287508e-38f);
    return -logf(-logf(v));
}

__global__ void gumbel_kernel(float* __restrict__ g) {
    int i = blockIdx.x * blockDim.x + threadIdx.x;
    if (i >= MM) return;
    unsigned x0 = 0u, x1 = (unsigned)i;
    threefry2x32_dev(0u, 42u, x0, x1);
    g[i] = bits_to_gumbel(x0 ^ x1);
}

// ---------------- init / segment softmax / scatter -------------------------------
__global__ void init_kernel(float* __restrict__ out,
                            unsigned* __restrict__ mxh, unsigned* __restrict__ mxs,
                            float* __restrict__ sh, float* __restrict__ ss) {
    int i = blockIdx.x * blockDim.x + threadIdx.x;
    if (i < BB * NN * HH) out[i] = 0.0f;
    if (i < NN * BB) { mxh[i] = ENC_NEG_INF; mxs[i] = ENC_NEG_INF; sh[i] = 0.0f; ss[i] = 0.0f; }
}

__global__ void prep_kernel(const float* __restrict__ logits, const float* __restrict__ g,
                            const int* __restrict__ src,
                            float* __restrict__ av,
                            unsigned* __restrict__ mxh, unsigned* __restrict__ mxs) {
    int f = blockIdx.x * blockDim.x + threadIdx.x;
    int e = f >> 1, b = f & 1;
    float l = logits[(size_t)b * EE + e];
    float a = (l + g[f]) / 0.1f;
    av[f] = a;
    int n2 = src[e] * BB + b;
    atomicMax(&mxh[n2], enc_f(a));
    atomicMax(&mxs[n2], enc_f(l));
}

__global__ void sum_kernel(const float* __restrict__ logits, const float* __restrict__ av,
                           const int* __restrict__ src,
                           const unsigned* __restrict__ mxh, const unsigned* __restrict__ mxs,
                           float* __restrict__ sh, float* __restrict__ ss) {
    int f = blockIdx.x * blockDim.x + threadIdx.x;
    int e = f >> 1, b = f & 1;
    int n2 = src[e] * BB + b;
    atomicAdd(&sh[n2], expf(av[f] - dec_f(mxh[n2])));
    atomicAdd(&ss[n2], expf(logits[(size_t)b * EE + e] - dec_f(mxs[n2])));
}

__global__ void scatter_kernel(const float* __restrict__ h,
                               const int* __restrict__ tgt, const int* __restrict__ src,
                               const float* __restrict__ logits, const float* __restrict__ av,
                               const unsigned* __restrict__ mxh, const unsigned* __restrict__ mxs,
                               const float* __restrict__ sh, const float* __restrict__ ss,
                               float* __restrict__ out) {
    int e = blockIdx.x;
    int j = threadIdx.x;
    int s = src[e], t = tgt[e];
    #pragma unroll
    for (int b = 0; b < BB; b++) {
        int n2 = s * BB + b;
        float a = av[e * BB + b];
        float l = logits[(size_t)b * EE + e];
        float w = (expf(a - dec_f(mxh[n2])) / sh[n2]) * (expf(l - dec_f(mxs[n2])) / ss[n2]);
        float hv = h[((size_t)b * NN + s) * HH + j];
        atomicAdd(&out[((size_t)b * NN + t) * HH + j], hv * w);
    }
}

// ---------------- host orchestration ---------------------------------------------
extern "C" void kernel_launch(void* const* d_in, const int* in_sizes, int n_in,
                              void* d_out, int out_size) {
    static const int map_ins[20]   = {0,1,2,3,4,5,6,7,8,9,10,11,12,13,14,15,16,17,18,19};
    static const int map_alpha[20] = {10,9,17,13,6,2,16,12,5,1,19,15,8,4,18,14,7,3,11,0};
    const int* mp = (in_sizes[0] == BB * NN * HH) ? map_ins : map_alpha;

    const float* h   = (const float*)d_in[mp[0]];
    const int* ei    = (const int*)d_in[mp[1]];
    const int* tgt   = ei;
    const int* src   = ei + EE;
    const float* wih0f = (const float*)d_in[mp[2]];
    const float* whh0f = (const float*)d_in[mp[3]];
    const float* bih0f = (const float*)d_in[mp[4]];
    const float* bhh0f = (const float*)d_in[mp[5]];
    const float* wih0b = (const float*)d_in[mp[6]];
    const float* whh0b = (const float*)d_in[mp[7]];
    const float* bih0b = (const float*)d_in[mp[8]];
    const float* bhh0b = (const float*)d_in[mp[9]];
    const float* wih1f = (const float*)d_in[mp[10]];
    const float* bih1f = (const float*)d_in[mp[12]];
    const float* bhh1f = (const float*)d_in[mp[13]];
    const float* wih1b = (const float*)d_in[mp[14]];
    const float* whh1b = (const float*)d_in[mp[15]];
    const float* bih1b = (const float*)d_in[mp[16]];
    const float* bhh1b = (const float*)d_in[mp[17]];
    const float* wcon  = (const float*)d_in[mp[18]];
    const float* bcon  = (const float*)d_in[mp[19]];
    float* out = (float*)d_out;

    float *gi, *gh, *y0, *y1, *hhb, *hb1, *logits, *av, *gum, *sh, *ss;
    unsigned *mxh, *mxs;
    __nv_bfloat16 *x0h, *x0l, *x1h, *x1l, *y0h, *y0l, *y1h, *y1l, *hb1h, *hb1l;
    __nv_bfloat16 *wpkh, *wpkl;
    cudaGetSymbolAddress((void**)&gi, g_gi);
    cudaGetSymbolAddress((void**)&gh, g_gh);
    cudaGetSymbolAddress((void**)&y0, g_y0);
    cudaGetSymbolAddress((void**)&y1, g_y1);
    cudaGetSymbolAddress((void**)&hhb, g_hh);
    cudaGetSymbolAddress((void**)&hb1, g_hb1);
    cudaGetSymbolAddress((void**)&logits, g_logits);
    cudaGetSymbolAddress((void**)&av, g_av);
    cudaGetSymbolAddress((void**)&gum, g_gum);
    cudaGetSymbolAddress((void**)&mxh, g_mxh);
    cudaGetSymbolAddress((void**)&mxs, g_mxs);
    cudaGetSymbolAddress((void**)&sh, g_sh);
    cudaGetSymbolAddress((void**)&ss, g_ss);
    cudaGetSymbolAddress((void**)&x0h, g_x0h);
    cudaGetSymbolAddress((void**)&x0l, g_x0l);
    cudaGetSymbolAddress((void**)&x1h, g_x1h);
    cudaGetSymbolAddress((void**)&x1l, g_x1l);
    cudaGetSymbolAddress((void**)&y0h, g_y0h);
    cudaGetSymbolAddress((void**)&y0l, g_y0l);
    cudaGetSymbolAddress((void**)&y1h, g_y1h);
    cudaGetSymbolAddress((void**)&y1l, g_y1l);
    cudaGetSymbolAddress((void**)&hb1h, g_hb1h);
    cudaGetSymbolAddress((void**)&hb1l, g_hb1l);
    cudaGetSymbolAddress((void**)&wpkh, g_wpk_h);
    cudaGetSymbolAddress((void**)&wpkl, g_wpk_l);

    cudaFuncSetAttribute(sgemm_mma, cudaFuncAttributeMaxDynamicSharedMemorySize,
                         2 * STAGE_B);

    // packed weight offsets
    __nv_bfloat16 *pw0f = wpkh + 0,      *pw0f_l = wpkl + 0;        // wih0f
    __nv_bfloat16 *ph0f = wpkh + 49152,  *ph0f_l = wpkl + 49152;    // whh0f
    __nv_bfloat16 *pw0b = wpkh + 98304,  *pw0b_l = wpkl + 98304;    // wih0b
    __nv_bfloat16 *ph0b = wpkh + 147456, *ph0b_l = wpkl + 147456;   // whh0b
    __nv_bfloat16 *ph1b = wpkh + 196608, *ph1b_l = wpkl + 196608;   // whh1b
    __nv_bfloat16 *pw1f = wpkh + 245760, *pw1f_l = wpkl + 245760;   // wih1f (K=256)
    __nv_bfloat16 *pw1b = wpkh + 344064, *pw1b_l = wpkl + 344064;   // wih1b (K=256)

    pack_w<<<49152 / 256, 256>>>(wih0f, 128, pw0f, pw0f_l);
    pack_w<<<49152 / 256, 256>>>(whh0f, 128, ph0f, ph0f_l);
    pack_w<<<49152 / 256, 256>>>(wih0b, 128, pw0b, pw0b_l);
    pack_w<<<49152 / 256, 256>>>(whh0b, 128, ph0b, ph0b_l);
    pack_w<<<49152 / 256, 256>>>(whh1b, 128, ph1b, ph1b_l);
    pack_w<<<98304 / 256, 256>>>(wih1f, 256, pw1f, pw1f_l);
    pack_w<<<98304 / 256, 256>>>(wih1b, 256, pw1b, pw1b_l);

    dim3 gemmGrid(3, 2000);
    const int PW_BLOCKS = (MM * 128) / 256;
    const int SMEM = 2 * STAGE_B;

    gather_kernel<<<(MM * 32) / 256, 256>>>((const float4*)h, tgt, src,
                                            x0h, x0l, x1h, x1l);

    // ---- layer 0 forward: f0 = cell(x0, 0) ; f1 = cell(x1, f0) ----
    sgemm_mma<<<gemmGrid, 256, SMEM>>>(x0h, x0l, 128, pw0f, pw0f_l, 4, gi);
    gru_pointwise<<<PW_BLOCKS, 256>>>(gi, nullptr, nullptr, 0, bih0f, bhh0f,
                                      y0, 256, y0h, y0l, 256);

    sgemm_mma<<<gemmGrid, 256, SMEM>>>(x1h, x1l, 128, pw0f, pw0f_l, 4, gi);
    sgemm_mma<<<gemmGrid, 256, SMEM>>>(y0h, y0l, 256, ph0f, ph0f_l, 4, gh);
    gru_pointwise<<<PW_BLOCKS, 256>>>(gi, gh, y0, 256, bih0f, bhh0f,
                                      y1, 256, y1h, y1l, 256);

    // ---- layer 0 backward: b1 = cell(x1, 0) ; b0 = cell(x0, b1) ----
    sgemm_mma<<<gemmGrid, 256, SMEM>>>(x1h, x1l, 128, pw0b, pw0b_l, 4, gi);
    gru_pointwise<<<PW_BLOCKS, 256>>>(gi, nullptr, nullptr, 0, bih0b, bhh0b,
                                      y1 + 128, 256, y1h + 128, y1l + 128, 256);

    sgemm_mma<<<gemmGrid, 256, SMEM>>>(x0h, x0l, 128, pw0b, pw0b_l, 4, gi);
    sgemm_mma<<<gemmGrid, 256, SMEM>>>(y1h + 128, y1l + 128, 256, ph0b, ph0b_l, 4, gh);
    gru_pointwise<<<PW_BLOCKS, 256>>>(gi, gh, y1 + 128, 256, bih0b, bhh0b,
                                      y0 + 128, 256, y0h + 128, y0l + 128, 256);

    // ---- layer 1: f0' = cellf(y0,0) ; b1' = cellb(y1,0) ; b0' = cellb(y0,b1') ----
    sgemm_mma<<<gemmGrid, 256, SMEM>>>(y0h, y0l, 256, pw1f, pw1f_l, 8, gi);
    gru_pointwise<<<PW_BLOCKS, 256>>>(gi, nullptr, nullptr, 0, bih1f, bhh1f,
                                      hhb, 256, nullptr, nullptr, 0);

    sgemm_mma<<<gemmGrid, 256, SMEM>>>(y1h, y1l, 256, pw1b, pw1b_l, 8, gi);
    gru_pointwise<<<PW_BLOCKS, 256>>>(gi, nullptr, nullptr, 0, bih1b, bhh1b,
                                      hb1, 128, hb1h, hb1l, 128);

    sgemm_mma<<<gemmGrid, 256, SMEM>>>(y0h, y0l, 256, pw1b, pw1b_l, 8, gi);
    sgemm_mma<<<gemmGrid, 256, SMEM>>>(hb1h, hb1l, 128, ph1b, ph1b_l, 4, gh);
    gru_pointwise<<<PW_BLOCKS, 256>>>(gi, gh, hb1, 128, bih1b, bhh1b,
                                      hhb + 128, 256, nullptr, nullptr, 0);

    // ---- logits, gumbel, segment softmaxes, weighted scatter ----
    logits_kernel<<<(MM * 32) / 256, 256>>>(hhb, wcon, bcon, logits);
    gumbel_kernel<<<(MM + 255) / 256, 256>>>(gum);
    init_kernel<<<(BB * NN * HH + 255) / 256, 256>>>(out, mxh, mxs, sh, ss);
    prep_kernel<<<MM / 256, 256>>>(logits, gum, src, av, mxh, mxs);
    sum_kernel<<<MM / 256, 256>>>(logits, av, src, mxh, mxs, sh, ss);
    scatter_kernel<<<EE, 128>>>(h, tgt, src, logits, av, mxh, mxs, sh, ss, out);
}